// round 4
// baseline (speedup 1.0000x reference)
#include <cuda_runtime.h>

// Reference math: dx = 0  =>  s^2 = -dt^2 <= 0 everywhere  =>  spacelike_mask == 0
// => penalty == 0 => total_loss = base_loss + 0.01 * 0 = base_loss (bit-exact in fp32).
// attn_weights (d_in[0], ~302M floats) is dead input.
//
// FINAL: captured graph = one 4-byte D2D memcpy node. Measured floor ~4.7 µs
// with a 256 ns harness timer quantum (all runs are 18-19 ticks):
//   kernel node        4.864 µs
//   memcpy D2D         4.608 µs   <- best tick, this variant
//   memcpy Default     4.864 µs   (same node post-capture; quantization noise)
// No removable node (d_out poisoned pre-timing => write is mandatory), no
// cheaper node type, no fewer bytes. Converged.

extern "C" void kernel_launch(void* const* d_in, const int* in_sizes, int n_in,
                              void* d_out, int out_size) {
    // d_in[1] = base_loss scalar f32; d_out[0] = total_loss f32
    cudaMemcpyAsync(d_out, d_in[1], sizeof(float),
                    cudaMemcpyDeviceToDevice, (cudaStream_t)0);
}

// round 5
// speedup vs baseline: 1.5000x; 1.5000x over previous
#include <cuda_runtime.h>

// Reference math: dx = 0  =>  s^2 = -dt^2 <= 0 everywhere  =>  spacelike_mask == 0
// => penalty == 0 => total_loss = base_loss + 0.01 * 0 = base_loss (bit-exact in fp32).
// attn_weights (d_in[0], ~302M floats) is dead input.
//
// R5: variance discrimination. Samples so far (256 ns timer quantum):
//   memcpy node (CE path): 4.608, 4.864, 6.912 µs  (mean 5.46, has tail)
//   kernel node (SM path): 4.864 µs                (one sample)
// Hypothesis: the memcpy node's copy-engine cross-engine wait/signal is the
// source of the 6.9 µs tail; a pure SM-path kernel node avoids it.
// Predicted: 4.4-5.4 µs, no >6.5 µs tail.

__global__ __launch_bounds__(32)
void spacetime_loss_copy(const float* __restrict__ base_loss,
                         float* __restrict__ out) {
    if (threadIdx.x == 0) out[0] = base_loss[0];
}

extern "C" void kernel_launch(void* const* d_in, const int* in_sizes, int n_in,
                              void* d_out, int out_size) {
    // d_in[1] = base_loss scalar f32; d_out[0] = total_loss f32
    spacetime_loss_copy<<<1, 32>>>((const float*)d_in[1], (float*)d_out);
}